// round 2
// baseline (speedup 1.0000x reference)
#include <cuda_runtime.h>
#include <cstdint>

// BinaryConv2d: x (8,16,1024,1024) f32, weight (16,16,3,3) in {0,1} -> +/-1
// stride (2,2), pad (1,1) -> out (8,16,512,512)
//
// f32x2 (FFMA2) conv, oc-pair packed accumulators, 3-stage cp.async pipeline,
// hoisted prefetch addressing, vectorized LDS.

#define N_BATCH 8
#define C_IN    16
#define C_OUT   16
#define IN_HW   1024
#define OUT_HW  512

#define TH 16              // output rows per block
#define TW 32              // output cols per block
#define NTHREADS 128       // 8 x-groups * 16 rows

#define TILE_H  33         // 2*TH + 1 input rows
#define TILE_W  65         // valid input cols
#define TILE_WP 68         // padded row stride (272B = 17*16B, aligned)
#define SLOTS   (TILE_H * TILE_WP)      // 2244
#define BUF_ELEMS 2304                  // padded so dummy cp.async stays in-bounds
#define NPREF   18                      // ceil(BUF_ELEMS / NTHREADS)

__device__ __forceinline__ unsigned long long bcast2(float x) {
    unsigned long long r;
    asm("mov.b64 %0, {%1, %1};" : "=l"(r) : "f"(x));
    return r;
}

__device__ __forceinline__ void ffma2(unsigned long long& acc,
                                      unsigned long long a,
                                      unsigned long long b) {
    asm("fma.rn.f32x2 %0, %1, %2, %0;" : "+l"(acc) : "l"(a), "l"(b));
}

__device__ __forceinline__ float2 unpack2(unsigned long long v) {
    float2 f;
    asm("mov.b64 {%0, %1}, %2;" : "=f"(f.x), "=f"(f.y) : "l"(v));
    return f;
}

__device__ __forceinline__ void cp_async_zfill(uint32_t saddr, const float* gptr, int sz) {
    asm volatile("cp.async.ca.shared.global [%0], [%1], 4, %2;\n"
                 :: "r"(saddr), "l"(gptr), "r"(sz));
}

__global__ void __launch_bounds__(NTHREADS, 4)
binconv_kernel(const float* __restrict__ x,
               const float* __restrict__ w,
               float* __restrict__ out) {
    __shared__ __align__(16) float s_in[3][BUF_ELEMS];
    __shared__ __align__(16) float s_sgn[C_IN * 9 * C_OUT];   // [c][tap][oc]

    const int tid = threadIdx.x;
    const int tx  = tid & 7;      // x group of 4 output px
    const int ty  = tid >> 3;     // output row in tile

    const int n  = blockIdx.z;
    const int y0 = blockIdx.y * TH;
    const int x0 = blockIdx.x * TW;

    // ---- decode weights into shared sign table (oc fastest, pair-packed) ----
    #pragma unroll
    for (int idx = tid; idx < C_OUT * C_IN * 9; idx += NTHREADS) {
        int oc  = idx / (C_IN * 9);
        int rem = idx - oc * (C_IN * 9);          // c*9 + tap
        s_sgn[rem * C_OUT + oc] = (w[idx] == 1.0f) ? 1.0f : -1.0f;
    }

    // ---- hoisted prefetch addressing: per-slot gmem offsets (channel-invariant) ----
    const int gy0 = 2 * y0 - 1;
    const int gx0 = 2 * x0 - 1;
    const float* xn = x + (size_t)n * C_IN * IN_HW * IN_HW;

    int off[NPREF];
    #pragma unroll
    for (int i = 0; i < NPREF; ++i) {
        int idx = tid + NTHREADS * i;
        int row = idx / TILE_WP;                  // constant-division, computed once
        int col = idx - row * TILE_WP;
        int gy = gy0 + row;
        int gx = gx0 + col;
        bool ok = (idx < SLOTS) && (col < TILE_W) &&
                  ((unsigned)gy < (unsigned)IN_HW) && ((unsigned)gx < (unsigned)IN_HW);
        off[i] = ok ? (gy * IN_HW + gx) : -1;
    }

    const uint32_t sbase = (uint32_t)__cvta_generic_to_shared(&s_in[0][0]) + 4u * tid;

    auto prefetch = [&](int c, int pi) {
        const float* xc = xn + ((size_t)c << 20);
        uint32_t sb = sbase + (uint32_t)pi * (BUF_ELEMS * 4);
        #pragma unroll
        for (int i = 0; i < NPREF; ++i) {
            int o = off[i];
            const float* src = xc + (o < 0 ? 0 : o);
            cp_async_zfill(sb + 512u * i, src, o < 0 ? 0 : 4);
        }
        asm volatile("cp.async.commit_group;\n");
    };

    // accumulators: [oc_pair 0..7][px 0..3] packed f32x2
    unsigned long long acc[8][4];
    #pragma unroll
    for (int i = 0; i < 8; ++i)
        #pragma unroll
        for (int p = 0; p < 4; ++p)
            acc[i][p] = 0ull;

    // ---- 3-stage pipeline: prefetch distance 2, one sync per channel ----
    prefetch(0, 0);
    prefetch(1, 1);

    int ci = 0;   // compute buffer index
    int pi = 2;   // prefetch target index

    #pragma unroll 1
    for (int c = 0; c < C_IN; ++c) {
        if (c == C_IN - 1) {
            asm volatile("cp.async.wait_group 0;\n");
        } else {
            asm volatile("cp.async.wait_group 1;\n");
        }
        __syncthreads();   // data(c) visible to all; everyone done reading buf(pi)

        if (c + 2 < C_IN)
            prefetch(c + 2, pi);

        const float* bp = &s_in[0][0] + ci * BUF_ELEMS;
        const float* sgn_c = s_sgn + c * 9 * C_OUT;

        #pragma unroll
        for (int r = 0; r < 3; ++r) {
            const float* rp = bp + (2 * ty + r) * TILE_WP + 8 * tx;
            float4 A = *(const float4*)rp;          // cols 0..3
            float4 B = *(const float4*)(rp + 4);    // cols 4..7
            float  xs = rp[8];                      // col 8

            unsigned long long xv[9];
            xv[0] = bcast2(A.x); xv[1] = bcast2(A.y);
            xv[2] = bcast2(A.z); xv[3] = bcast2(A.w);
            xv[4] = bcast2(B.x); xv[5] = bcast2(B.y);
            xv[6] = bcast2(B.z); xv[7] = bcast2(B.w);
            xv[8] = bcast2(xs);

            #pragma unroll
            for (int j = 0; j < 3; ++j) {
                const ulonglong2* sp =
                    (const ulonglong2*)(sgn_c + (r * 3 + j) * C_OUT);
                ulonglong2 s0 = sp[0];   // broadcast LDS.128, conflict-free
                ulonglong2 s1 = sp[1];
                unsigned long long sv[8] = { s0.x, s0.y, s1.x, s1.y, 0, 0, 0, 0 };
                ulonglong2 s2 = sp[2];
                ulonglong2 s3 = sp[3];
                sv[4] = s2.x; sv[5] = s2.y; sv[6] = s3.x; sv[7] = s3.y;

                #pragma unroll
                for (int p = 0; p < 4; ++p) {
                    unsigned long long xvp = xv[2 * p + j];
                    #pragma unroll
                    for (int i = 0; i < 8; ++i)
                        ffma2(acc[i][p], xvp, sv[i]);
                }
            }
        }

        ci = (ci == 2) ? 0 : ci + 1;
        pi = (pi == 2) ? 0 : pi + 1;
    }

    // ---- writeout: 16 oc x 4 consecutive x -> float4 per oc ----
    const int oy = y0 + ty;
    const int ox = x0 + 4 * tx;
    float* ob = out + (((size_t)n * C_OUT) * OUT_HW + oy) * OUT_HW + ox;

    #pragma unroll
    for (int i = 0; i < 8; ++i) {
        float2 f0 = unpack2(acc[i][0]);
        float2 f1 = unpack2(acc[i][1]);
        float2 f2 = unpack2(acc[i][2]);
        float2 f3 = unpack2(acc[i][3]);
        float4 lo = make_float4(f0.x, f1.x, f2.x, f3.x);
        float4 hi = make_float4(f0.y, f1.y, f2.y, f3.y);
        *(float4*)(ob + (size_t)(2 * i)     * OUT_HW * OUT_HW) = lo;
        *(float4*)(ob + (size_t)(2 * i + 1) * OUT_HW * OUT_HW) = hi;
    }
}

extern "C" void kernel_launch(void* const* d_in, const int* in_sizes, int n_in,
                              void* d_out, int out_size) {
    const float* x = (const float*)d_in[0];
    const float* w = (const float*)d_in[1];
    float* out = (float*)d_out;

    dim3 grid(OUT_HW / TW, OUT_HW / TH, N_BATCH);   // (16, 32, 8)
    dim3 block(NTHREADS);
    binconv_kernel<<<grid, block>>>(x, w, out);
}

// round 3
// speedup vs baseline: 1.3023x; 1.3023x over previous
#include <cuda_runtime.h>
#include <cstdint>

// BinaryConv2d: x (8,16,1024,1024) f32, weight (16,16,3,3) in {0,1} -> +/-1
// stride (2,2), pad (1,1) -> out (8,16,512,512)
//
// R3: warp-private input tiles (no block barriers in main loop),
// aligned 16B cp.async prefetch (edge column split off), distance-2
// 3-buffer per-warp pipeline, FFMA2 (f32x2) oc-pair-packed accumulators.

#define N_BATCH 8
#define C_IN    16
#define C_OUT   16
#define IN_HW   1024
#define OUT_HW  512

#define TH 16              // output rows per block (4 per warp)
#define TW 32              // output cols per block
#define NTHREADS 128
#define NBUF 3

#define ROW_STRIDE 72                   // bulk row stride (floats), 288B
#define BUF_FLOATS 660                  // 9*72 bulk + 9 edge + pad (2640B, 16B mult)
#define EDGE_OFF   648                  // float offset of edge column array

__device__ __forceinline__ unsigned long long bcast2(float x) {
    unsigned long long r;
    asm("mov.b64 %0, {%1, %1};" : "=l"(r) : "f"(x));
    return r;
}

__device__ __forceinline__ void ffma2(unsigned long long& acc,
                                      unsigned long long a,
                                      unsigned long long b) {
    asm("fma.rn.f32x2 %0, %1, %2, %0;" : "+l"(acc) : "l"(a), "l"(b));
}

__device__ __forceinline__ float2 unpack2(unsigned long long v) {
    float2 f;
    asm("mov.b64 {%0, %1}, %2;" : "=f"(f.x), "=f"(f.y) : "l"(v));
    return f;
}

__global__ void __launch_bounds__(NTHREADS, 4)
binconv_kernel(const float* __restrict__ x,
               const float* __restrict__ w,
               float* __restrict__ out) {
    __shared__ __align__(16) float s_tile[4][NBUF][BUF_FLOATS];
    __shared__ __align__(16) float s_sgn[C_IN * 9 * C_OUT];   // [c][tap][oc]

    const int tid  = threadIdx.x;
    const int wrp  = tid >> 5;
    const int lane = tid & 31;
    const int tx   = lane & 7;          // x-group (4 output px)
    const int ty   = (lane >> 3) & 3;   // output row within warp band

    const int n  = blockIdx.z;
    const int y0 = blockIdx.y * TH;
    const int x0 = blockIdx.x * TW;

    // ---- decode weights into shared sign table (oc fastest) ----
    #pragma unroll
    for (int idx = tid; idx < C_OUT * C_IN * 9; idx += NTHREADS) {
        int oc  = idx / (C_IN * 9);
        int rem = idx - oc * (C_IN * 9);          // c*9 + tap
        s_sgn[rem * C_OUT + oc] = (w[idx] == 1.0f) ? 1.0f : -1.0f;
    }
    __syncthreads();   // only barrier: sign table ready

    // ---- per-warp geometry ----
    const int gy0w = 2 * (y0 + 4 * wrp) - 1;   // first input row of this warp's band
    const int gx1  = 2 * x0;                   // aligned bulk col base (= gx0+1)
    const bool edge_col_ok = (gx1 > 0);        // edge col gx1-1 valid?

    const float* xn = x + ((size_t)n << 24);
    // gbase: points at (row gy0w, col gx1) of channel 0 (may be "before" array; guarded)
    const float* gbase = xn + (ptrdiff_t)gy0w * IN_HW + gx1;

    const int prow = 2 * ((lane >> 4) ? 0 : 0); (void)prow; // (placeholder removed below)
    const int brow_hi = lane >> 4;             // 0/1: row parity within k-step
    const int bcol    = (lane & 15) * 4;       // bulk col (floats)

    const uint32_t smem_w =
        (uint32_t)__cvta_generic_to_shared(&s_tile[wrp][0][0]);

    auto prefetch = [&](int c, int buf) {
        const float* gc = gbase + ((size_t)c << 20);
        uint32_t sb = smem_w + (uint32_t)buf * (BUF_FLOATS * 4);
        #pragma unroll
        for (int k = 0; k < 5; ++k) {
            int row = 2 * k + brow_hi;
            if (k < 4 || brow_hi == 0) {       // rows 0..8 only
                bool ok = (gy0w + row) >= 0;   // bottom always in-bounds
                const float* src = ok ? (gc + row * IN_HW + bcol) : xn;
                asm volatile("cp.async.cg.shared.global [%0], [%1], 16, %2;\n"
                             :: "r"(sb + (uint32_t)(row * ROW_STRIDE + bcol) * 4u),
                                "l"(src), "r"(ok ? 16 : 0));
            }
        }
        if (lane < 9) {
            bool ok = edge_col_ok && ((gy0w + lane) >= 0);
            const float* src = ok ? (gc + lane * IN_HW - 1) : xn;
            asm volatile("cp.async.ca.shared.global [%0], [%1], 4, %2;\n"
                         :: "r"(sb + (uint32_t)(EDGE_OFF + lane) * 4u),
                            "l"(src), "r"(ok ? 4 : 0));
        }
        asm volatile("cp.async.commit_group;\n");
    };

    // accumulators: [oc_pair 0..7][px 0..3] packed f32x2
    unsigned long long acc[8][4];
    #pragma unroll
    for (int i = 0; i < 8; ++i)
        #pragma unroll
        for (int p = 0; p < 4; ++p)
            acc[i][p] = 0ull;

    // ---- per-warp pipeline: distance 2, 3 buffers, no block barriers ----
    prefetch(0, 0);
    prefetch(1, 1);

    int ci = 0;   // compute buffer
    int pi = 2;   // prefetch target buffer

    #pragma unroll 1
    for (int c = 0; c < C_IN; ++c) {
        if (c + 2 < C_IN) {
            prefetch(c + 2, pi);
            asm volatile("cp.async.wait_group 2;\n");
        } else if (c + 1 < C_IN) {
            asm volatile("cp.async.wait_group 1;\n");
        } else {
            asm volatile("cp.async.wait_group 0;\n");
        }
        __syncwarp();

        const float* bp = &s_tile[wrp][0][0] + ci * BUF_FLOATS;
        const float* sgn_c = s_sgn + c * 9 * C_OUT;

        #pragma unroll
        for (int r = 0; r < 3; ++r) {
            const int irow = 2 * ty + r;
            const float* rpb = bp + irow * ROW_STRIDE;
            const float* pfirst = (tx == 0) ? (bp + EDGE_OFF + irow)
                                            : (rpb + 8 * tx - 1);
            float xfirst = *pfirst;
            float4 A = *(const float4*)(rpb + 8 * tx);
            float4 B = *(const float4*)(rpb + 8 * tx + 4);

            unsigned long long xv[9];
            xv[0] = bcast2(xfirst);
            xv[1] = bcast2(A.x); xv[2] = bcast2(A.y);
            xv[3] = bcast2(A.z); xv[4] = bcast2(A.w);
            xv[5] = bcast2(B.x); xv[6] = bcast2(B.y);
            xv[7] = bcast2(B.z); xv[8] = bcast2(B.w);

            #pragma unroll
            for (int j = 0; j < 3; ++j) {
                const ulonglong2* sp =
                    (const ulonglong2*)(sgn_c + (r * 3 + j) * C_OUT);
                ulonglong2 s0 = sp[0];   // broadcast LDS.128
                ulonglong2 s1 = sp[1];
                ulonglong2 s2 = sp[2];
                ulonglong2 s3 = sp[3];
                unsigned long long sv[8] =
                    { s0.x, s0.y, s1.x, s1.y, s2.x, s2.y, s3.x, s3.y };

                #pragma unroll
                for (int p = 0; p < 4; ++p) {
                    unsigned long long xvp = xv[2 * p + j];
                    #pragma unroll
                    for (int i = 0; i < 8; ++i)
                        ffma2(acc[i][p], xvp, sv[i]);
                }
            }
        }
        __syncwarp();

        ci = (ci == 2) ? 0 : ci + 1;
        pi = (pi == 2) ? 0 : pi + 1;
    }

    // ---- writeout: 16 oc x 4 consecutive x -> float4 per oc ----
    const int oy = y0 + 4 * wrp + ty;
    const int ox = x0 + 4 * tx;
    float* ob = out + (((size_t)n * C_OUT) * OUT_HW + oy) * OUT_HW + ox;

    #pragma unroll
    for (int i = 0; i < 8; ++i) {
        float2 f0 = unpack2(acc[i][0]);
        float2 f1 = unpack2(acc[i][1]);
        float2 f2 = unpack2(acc[i][2]);
        float2 f3 = unpack2(acc[i][3]);
        float4 lo = make_float4(f0.x, f1.x, f2.x, f3.x);
        float4 hi = make_float4(f0.y, f1.y, f2.y, f3.y);
        *(float4*)(ob + (size_t)(2 * i)     * OUT_HW * OUT_HW) = lo;
        *(float4*)(ob + (size_t)(2 * i + 1) * OUT_HW * OUT_HW) = hi;
    }
}

extern "C" void kernel_launch(void* const* d_in, const int* in_sizes, int n_in,
                              void* d_out, int out_size) {
    const float* x = (const float*)d_in[0];
    const float* w = (const float*)d_in[1];
    float* out = (float*)d_out;

    dim3 grid(OUT_HW / TW, OUT_HW / TH, N_BATCH);   // (16, 32, 8)
    dim3 block(NTHREADS);
    binconv_kernel<<<grid, block>>>(x, w, out);
}